// round 14
// baseline (speedup 1.0000x reference)
#include <cuda_runtime.h>
#include <cuda_bf16.h>
#include <cstdint>

#define C 128
#define LDW 132
#define WSTR 136
#define WPL (64 * WSTR)
#define THREADS 512
#define EPSF 1e-8f

__device__ float g_Mm[C * C];
__device__ float g_Md[C * C];
// bake order: 0 Wgcn, 1 Mm, 2 Wvm, 3 Md, 4 Wvd, 5 W1  (copy order uses 0,1,3,2,4,5)
__device__ __align__(16) uint32_t g_BH[6][WPL];
__device__ __align__(16) uint32_t g_BL[6][WPL];

// ---- smem u32 layout ----
#define U_R2A 16
#define U_R3A (U_R2A + 8448)
#define U_R2B (U_R3A + 8448)
#define U_R3B (U_R2B + 8448)
#define U_WS  (U_R3B + 8448)      // single weight slot [WH | WL]
#define U_RED (U_WS + 2 * WPL)    // 8 x 256 floats
#define U_WSM (U_RED + 2048)      // 8 x 64 floats
#define U_ABB (U_WSM + 512)       // aB[128], bB[128]
#define U_W2  (U_ABB + 256)
#define U_TOT (U_W2 + 128)        // 54160 u32 = 216,640 B

__device__ __forceinline__ uint32_t s2u(const void* p) {
    uint32_t a;
    asm("{ .reg .u64 t; cvta.to.shared.u64 t, %1; cvt.u32.u64 %0, t; }" : "=r"(a) : "l"(p));
    return a;
}
#define MBAR_INIT(a, c) asm volatile("mbarrier.init.shared.b64 [%0], %1;" ::"r"(a), "r"(c) : "memory")
#define MBAR_EXPECT(a, b) \
    asm volatile("mbarrier.arrive.expect_tx.shared.b64 _, [%0], %1;" ::"r"(a), "r"(b) : "memory")
__device__ __forceinline__ void mbar_wait(uint32_t a, uint32_t par) {
    asm volatile(
        "{\n\t.reg .pred P;\n\tWL_%=:\n\t"
        "mbarrier.try_wait.parity.acquire.cta.shared::cta.b64 P, [%0], %1, 0x989680;\n\t"
        "@P bra.uni WD_%=;\n\tbra.uni WL_%=;\n\tWD_%=:\n\t}" ::"r"(a), "r"(par) : "memory");
}
__device__ __forceinline__ void bulk_g2s(uint32_t dst, const void* gsrc, uint32_t bytes,
                                         uint32_t mbar) {
    asm volatile(
        "{ .reg .u64 g; cvta.to.global.u64 g, %1;\n\t"
        "cp.async.bulk.shared::cluster.global.mbarrier::complete_tx::bytes [%0], [g], %2, [%3]; }"
        ::"r"(dst), "l"(gsrc), "r"(bytes), "r"(mbar) : "memory");
}

__device__ __forceinline__ void split_pack(float x0, float x1, uint32_t& h, uint32_t& l) {
    uint32_t u0 = __float_as_uint(x0), u1 = __float_as_uint(x1);
    h = __byte_perm(u0, u1, 0x7632);
    float l0 = x0 - __uint_as_float(u0 & 0xFFFF0000u);
    float l1 = x1 - __uint_as_float(u1 & 0xFFFF0000u);
    __nv_bfloat162 t = __floats2bfloat162_rn(l0, l1);
    l = *(uint32_t*)&t;
}
__device__ __forceinline__ uint2 pack2(float x, float y) {
    uint2 r;
    split_pack(x, y, r.x, r.y);
    return r;
}
__device__ __forceinline__ float2 unpack2(uint2 p) {
    float2 a = __bfloat1622float2(*(__nv_bfloat162*)&p.x);
    float2 b = __bfloat1622float2(*(__nv_bfloat162*)&p.y);
    return make_float2(a.x + b.x, a.y + b.y);
}
__device__ __forceinline__ void mma16816(float* d, const uint32_t* a, uint32_t b0, uint32_t b1) {
    asm volatile(
        "mma.sync.aligned.m16n8k16.row.col.f32.bf16.bf16.f32 "
        "{%0,%1,%2,%3}, {%4,%5,%6,%7}, {%8,%9}, {%0,%1,%2,%3};"
        : "+f"(d[0]), "+f"(d[1]), "+f"(d[2]), "+f"(d[3])
        : "r"(a[0]), "r"(a[1]), "r"(a[2]), "r"(a[3]), "r"(b0), "r"(b1));
}
#define MMA3(accn, bh0, bh1, bl0, bl1) \
    do {                               \
        mma16816(accn, ah, bh0, bh1);  \
        mma16816(accn, al, bh0, bh1);  \
        mma16816(accn, ah, bl0, bl1);  \
    } while (0)

// acc[nt][0..3]: rows (rb+g, rb+g+8), cols c32*32 + nt*8 + 2t (+1). W = slot base (WH | WL)
__device__ __forceinline__ void mma_block(const uint32_t* A, const uint32_t* W, float acc[4][4],
                                          int rb, int c32, int g, int t) {
    const uint32_t* pa = A + (rb + g) * LDW + 2 * t;
    const uint32_t* pb = W + t * WSTR + c32 * 32 + g * 4;
    const uint32_t* pc = pb + WPL;
#pragma unroll 2
    for (int k0 = 0; k0 < 8; k0++) {
        uint2 a0 = *(const uint2*)pa, a1 = *(const uint2*)(pa + 8 * LDW);
        uint2 a2 = *(const uint2*)(pa + 8), a3 = *(const uint2*)(pa + 8 * LDW + 8);
        uint4 bh0 = *(const uint4*)pb, bh1 = *(const uint4*)(pb + 4 * WSTR);
        uint4 bl0 = *(const uint4*)pc, bl1 = *(const uint4*)(pc + 4 * WSTR);
        uint32_t ah[4] = {a0.x, a1.x, a2.x, a3.x}, al[4] = {a0.y, a1.y, a2.y, a3.y};
        MMA3(acc[0], bh0.x, bh1.x, bl0.x, bl1.x);
        MMA3(acc[1], bh0.y, bh1.y, bl0.y, bl1.y);
        MMA3(acc[2], bh0.z, bh1.z, bl0.z, bl1.z);
        MMA3(acc[3], bh0.w, bh1.w, bl0.w, bl1.w);
        pa += 16;
        pb += 8 * WSTR;
        pc += 8 * WSTR;
    }
}
__device__ __forceinline__ void mma_block2(const uint32_t* A0, const uint32_t* A1,
                                           const uint32_t* W, float acc0[4][4], float acc1[4][4],
                                           int rb, int c32, int g, int t) {
    const uint32_t* pa = A0 + (rb + g) * LDW + 2 * t;
    const uint32_t* pq = A1 + (rb + g) * LDW + 2 * t;
    const uint32_t* pb = W + t * WSTR + c32 * 32 + g * 4;
    const uint32_t* pc = pb + WPL;
#pragma unroll 1
    for (int k0 = 0; k0 < 8; k0++) {
        uint4 bh0 = *(const uint4*)pb, bh1 = *(const uint4*)(pb + 4 * WSTR);
        uint4 bl0 = *(const uint4*)pc, bl1 = *(const uint4*)(pc + 4 * WSTR);
        {
            uint2 a0 = *(const uint2*)pa, a1 = *(const uint2*)(pa + 8 * LDW);
            uint2 a2 = *(const uint2*)(pa + 8), a3 = *(const uint2*)(pa + 8 * LDW + 8);
            uint32_t ah[4] = {a0.x, a1.x, a2.x, a3.x}, al[4] = {a0.y, a1.y, a2.y, a3.y};
            MMA3(acc0[0], bh0.x, bh1.x, bl0.x, bl1.x);
            MMA3(acc0[1], bh0.y, bh1.y, bl0.y, bl1.y);
            MMA3(acc0[2], bh0.z, bh1.z, bl0.z, bl1.z);
            MMA3(acc0[3], bh0.w, bh1.w, bl0.w, bl1.w);
        }
        {
            uint2 a0 = *(const uint2*)pq, a1 = *(const uint2*)(pq + 8 * LDW);
            uint2 a2 = *(const uint2*)(pq + 8), a3 = *(const uint2*)(pq + 8 * LDW + 8);
            uint32_t ah[4] = {a0.x, a1.x, a2.x, a3.x}, al[4] = {a0.y, a1.y, a2.y, a3.y};
            MMA3(acc1[0], bh0.x, bh1.x, bl0.x, bl1.x);
            MMA3(acc1[1], bh0.y, bh1.y, bl0.y, bl1.y);
            MMA3(acc1[2], bh0.z, bh1.z, bl0.z, bl1.z);
            MMA3(acc1[3], bh0.w, bh1.w, bl0.w, bl1.w);
        }
        pa += 16;
        pq += 16;
        pb += 8 * WSTR;
        pc += 8 * WSTR;
    }
}

// ---------------- prep ----------------
__global__ void precompute_M_kernel(const float* __restrict__ Wq_m, const float* __restrict__ Wk_m,
                                    const float* __restrict__ Wq_d, const float* __restrict__ Wk_d) {
    const float* Wq = blockIdx.y ? Wq_d : Wq_m;
    const float* Wk = blockIdx.y ? Wk_d : Wk_m;
    float* M = blockIdx.y ? g_Md : g_Mm;
    int i = blockIdx.x, t = threadIdx.x;
    __shared__ float qrow[C];
    qrow[t] = Wq[i * C + t];
    __syncthreads();
    const float* wkr = Wk + t * C;
    float a0 = 0.f, a1 = 0.f, a2 = 0.f, a3 = 0.f;
#pragma unroll 8
    for (int j = 0; j < C; j += 4) {
        a0 += qrow[j] * wkr[j];
        a1 += qrow[j + 1] * wkr[j + 1];
        a2 += qrow[j + 2] * wkr[j + 2];
        a3 += qrow[j + 3] * wkr[j + 3];
    }
    M[i * C + t] = ((a0 + a1) + (a2 + a3)) * 0.08838834764831845f;
}

__global__ void bake_kernel(const float* __restrict__ Wg, const float* __restrict__ Wvm,
                            const float* __restrict__ Wvd, const float* __restrict__ W1) {
    int w = blockIdx.y;
    const float* src = (w == 0) ? Wg : (w == 1) ? g_Mm : (w == 2) ? Wvm
                      : (w == 3) ? g_Md : (w == 4) ? Wvd : W1;
    int idx = blockIdx.x * blockDim.x + threadIdx.x;  // 0..8191
    int nt = idx & 3, g = (idx >> 2) & 7, c32 = (idx >> 5) & 3, k2 = idx >> 7;
    int n = c32 * 32 + nt * 8 + g;
    uint32_t h, l;
    split_pack(src[(2 * k2) * C + n], src[(2 * k2 + 1) * C + n], h, l);
    int dst = k2 * WSTR + (idx & 127);
    g_BH[w][dst] = h;
    g_BL[w][dst] = l;
}

// ---------------- fused: 128 rows per CTA (two 64-row sub-tiles) ----------------
__global__ void __launch_bounds__(THREADS, 1)
fused_kernel(const float* __restrict__ em, const float* __restrict__ ed,
             const float* __restrict__ W2, float* __restrict__ out) {
    extern __shared__ uint32_t sm[];
    const uint32_t sb = s2u(sm);
    const uint32_t mb = sb;
    uint32_t* R2[2] = {sm + U_R2A, sm + U_R2B};
    uint32_t* R3[2] = {sm + U_R3A, sm + U_R3B};
    uint32_t* WS = sm + U_WS;
    float* red = (float*)(sm + U_RED);   // [8][256]
    float* wSm = (float*)(sm + U_WSM);   // [8][64]
    float* aB = (float*)(sm + U_ABB);    // [128]
    float* bB = aB + 128;
    float* sW2 = (float*)(sm + U_W2);

    const int tid = threadIdx.x;
    const int w = tid >> 5, lane = tid & 31;
    const int g = lane >> 2, t = lane & 3;
    const int rb = (w & 3) * 16, c32 = w >> 2;
    const int r1 = rb + g, r2 = r1 + 8;
    const int cb = c32 * 32 + 2 * t;
    const int row4 = w * 4;
    const long base = (long)blockIdx.x * 128;

    auto copy_w = [&](int wi) {
        if (tid == 0) {
            MBAR_EXPECT(mb, 2u * WPL * 4);
            bulk_g2s(sb + U_WS * 4, &g_BH[wi][0], WPL * 4, mb);
            bulk_g2s(sb + (U_WS + WPL) * 4, &g_BL[wi][0], WPL * 4, mb);
        }
    };

    if (tid == 0) MBAR_INIT(mb, 1);
    __syncwarp();
    copy_w(0);  // Wgcn, completes phase 0
    if (tid < C) sW2[tid] = W2[tid];

    // adjacency + pack em/ed for both sub-tiles
#pragma unroll
    for (int tau = 0; tau < 2; tau++) {
#pragma unroll
        for (int rr = 0; rr < 4; rr++) {
            int r = row4 + rr;
            long gr = base + tau * 64 + r;
            const float* pe = em + gr * C;
            const float* pd = ed + gr * C;
            float2 e0 = *(const float2*)(pe + 2 * lane), e1 = *(const float2*)(pe + 2 * lane + 64);
            float2 d0 = *(const float2*)(pd + 2 * lane), d1 = *(const float2*)(pd + 2 * lane + 64);
            float sa = fabsf(e0.x - d0.x) + fabsf(e0.y - d0.y) + fabsf(e1.x - d1.x) +
                       fabsf(e1.y - d1.y);
            float q0 = e0.x * e0.x + e0.y * e0.y + e1.x * e1.x + e1.y * e1.y;
            float q1 = d0.x * d0.x + d0.y * d0.y + d1.x * d1.x + d1.y * d1.y;
            float dp = e0.x * d0.x + e0.y * d0.y + e1.x * d1.x + e1.y * d1.y;
#pragma unroll
            for (int o = 16; o; o >>= 1) {
                sa += __shfl_xor_sync(~0u, sa, o);
                q0 += __shfl_xor_sync(~0u, q0, o);
                q1 += __shfl_xor_sync(~0u, q1, o);
                dp += __shfl_xor_sync(~0u, dp, o);
            }
            if (lane == 0) {
                float m = sa;
                float cosv = dp / (sqrtf(q0 + EPSF) * sqrtf(q1 + EPSF));
                float cp = cosv > 0.f ? cosv : 0.01f * cosv;
                aB[tau * 64 + r] = fminf(1.f / (1.f + cp), 1.f / (1.f + m));
                bB[tau * 64 + r] = fminf(cp / (1.f + cp), m / (1.f + m));
            }
            *(uint2*)(R2[tau] + r * LDW + 2 * lane) = pack2(e0.x, e0.y);
            *(uint2*)(R2[tau] + r * LDW + 2 * lane + 64) = pack2(e1.x, e1.y);
            *(uint2*)(R3[tau] + r * LDW + 2 * lane) = pack2(d0.x, d0.y);
            *(uint2*)(R3[tau] + r * LDW + 2 * lane + 64) = pack2(d1.x, d1.y);
        }
    }
    __syncthreads();

    // ---------------- GCN (Wgcn, phase 0) ----------------
    mbar_wait(mb, 0);
    {
        float a0[2][4][4] = {}, a1[2][4][4] = {};
        mma_block2(R2[0], R3[0], WS, a0[0], a1[0], rb, c32, g, t);
        mma_block2(R2[1], R3[1], WS, a0[1], a1[1], rb, c32, g, t);
        __syncthreads();
        copy_w(1);  // Mm -> phase 1
#pragma unroll
        for (int tau = 0; tau < 2; tau++) {
            float aa1 = aB[tau * 64 + r1], bb1 = bB[tau * 64 + r1];
            float aa2 = aB[tau * 64 + r2], bb2 = bB[tau * 64 + r2];
            long g1r = base + tau * 64 + r1, g2r = base + tau * 64 + r2;
#pragma unroll
            for (int nt = 0; nt < 4; nt++) {
                int c = cb + nt * 8;
                float2 e1v = *(const float2*)(em + g1r * C + c);
                float2 e2v = *(const float2*)(em + g2r * C + c);
                float2 d1v = *(const float2*)(ed + g1r * C + c);
                float2 d2v = *(const float2*)(ed + g2r * C + c);
                *(uint2*)(R2[tau] + r1 * LDW + c) =
                    pack2(fmaxf(aa1 * a0[tau][nt][0] + bb1 * a1[tau][nt][0], 0.f) + e1v.x,
                          fmaxf(aa1 * a0[tau][nt][1] + bb1 * a1[tau][nt][1], 0.f) + e1v.y);
                *(uint2*)(R2[tau] + r2 * LDW + c) =
                    pack2(fmaxf(aa2 * a0[tau][nt][2] + bb2 * a1[tau][nt][2], 0.f) + e2v.x,
                          fmaxf(aa2 * a0[tau][nt][3] + bb2 * a1[tau][nt][3], 0.f) + e2v.y);
                *(uint2*)(R3[tau] + r1 * LDW + c) =
                    pack2(fmaxf(bb1 * a0[tau][nt][0] + aa1 * a1[tau][nt][0], 0.f) + d1v.x,
                          fmaxf(bb1 * a0[tau][nt][1] + aa1 * a1[tau][nt][1], 0.f) + d1v.y);
                *(uint2*)(R3[tau] + r2 * LDW + c) =
                    pack2(fmaxf(bb2 * a0[tau][nt][2] + aa2 * a1[tau][nt][2], 0.f) + d2v.x,
                          fmaxf(bb2 * a0[tau][nt][3] + aa2 * a1[tau][nt][3], 0.f) + d2v.y);
            }
        }
    }
    __syncthreads();

    // fold scores for one branch of one sub-tile; writes red slots (s0slot, s1slot)
    auto fold = [&](const float acc[4][4], const uint32_t* X, const float* F, int tau, int s0s,
                    int s1s) {
        long g1r = base + tau * 64 + r1, g2r = base + tau * 64 + r2;
        float s0a = 0.f, s1a = 0.f, s0b = 0.f, s1b = 0.f;
#pragma unroll
        for (int nt = 0; nt < 4; nt++) {
            int c = cb + nt * 8;
            float2 f1 = *(const float2*)(F + g1r * C + c);
            float2 f2 = *(const float2*)(F + g2r * C + c);
            float2 x1 = unpack2(*(const uint2*)(X + r1 * LDW + c));
            float2 x2 = unpack2(*(const uint2*)(X + r2 * LDW + c));
            s0a += acc[nt][0] * f1.x + acc[nt][1] * f1.y;
            s1a += acc[nt][0] * x1.x + acc[nt][1] * x1.y;
            s0b += acc[nt][2] * f2.x + acc[nt][3] * f2.y;
            s1b += acc[nt][2] * x2.x + acc[nt][3] * x2.y;
        }
#pragma unroll
        for (int o = 1; o < 4; o <<= 1) {
            s0a += __shfl_xor_sync(~0u, s0a, o);
            s1a += __shfl_xor_sync(~0u, s1a, o);
            s0b += __shfl_xor_sync(~0u, s0b, o);
            s1b += __shfl_xor_sync(~0u, s1b, o);
        }
        if (t == 0) {
            red[s0s * 256 + c32 * 64 + r1] = s0a;
            red[s1s * 256 + c32 * 64 + r1] = s1a;
            red[s0s * 256 + c32 * 64 + r2] = s0b;
            red[s1s * 256 + c32 * 64 + r2] = s1b;
        }
    };
    // u-pack one branch/sub-tile: X <- w0*F + w1*unpack(X), wSm pair p
    auto upack = [&](uint32_t* X, const float* F, int tau, int p) {
        long g1r = base + tau * 64 + r1, g2r = base + tau * 64 + r2;
        float w01 = wSm[2 * p * 64 + r1], w11 = wSm[(2 * p + 1) * 64 + r1];
        float w02 = wSm[2 * p * 64 + r2], w12 = wSm[(2 * p + 1) * 64 + r2];
#pragma unroll
        for (int nt = 0; nt < 4; nt++) {
            int c = cb + nt * 8;
            float2 f1 = *(const float2*)(F + g1r * C + c);
            float2 f2 = *(const float2*)(F + g2r * C + c);
            float2 x1 = unpack2(*(const uint2*)(X + r1 * LDW + c));
            float2 x2 = unpack2(*(const uint2*)(X + r2 * LDW + c));
            *(uint2*)(X + r1 * LDW + c) = pack2(w01 * f1.x + w11 * x1.x, w01 * f1.y + w11 * x1.y);
            *(uint2*)(X + r2 * LDW + c) = pack2(w02 * f2.x + w12 * x2.x, w02 * f2.y + w12 * x2.y);
        }
    };

    // ---------------- T_m (Mm, phase 1) ----------------
    mbar_wait(mb, 1);
    {
        float am0[4][4] = {}, am1[4][4] = {};
        mma_block(R2[0], WS, am0, rb, c32, g, t);
        mma_block(R2[1], WS, am1, rb, c32, g, t);
        __syncthreads();
        copy_w(3);  // Md -> phase 0
        fold(am0, R2[0], em, 0, 0, 1);
        fold(am1, R2[1], em, 1, 2, 3);
    }
    // ---------------- T_d (Md, phase 0) ----------------
    mbar_wait(mb, 0);
    {
        float ad0[4][4] = {}, ad1[4][4] = {};
        mma_block(R3[0], WS, ad0, rb, c32, g, t);
        mma_block(R3[1], WS, ad1, rb, c32, g, t);
        __syncthreads();
        copy_w(2);  // Wvm -> phase 1
        fold(ad0, R3[0], ed, 0, 4, 5);
        fold(ad1, R3[1], ed, 1, 6, 7);
    }
    __syncthreads();
    if (tid < 256) {  // softmax: pair p = tid>>6 (m_t0, m_t1, d_t0, d_t1)
        int p = tid >> 6, r = tid & 63;
        const float* p0 = red + (2 * p) * 256 + r;
        const float* p1 = red + (2 * p + 1) * 256 + r;
        float S0 = p0[0] + p0[64] + p0[128] + p0[192];
        float S1 = p1[0] + p1[64] + p1[128] + p1[192];
        float mx = fmaxf(S0, S1);
        float e0 = expf(S0 - mx), e1 = expf(S1 - mx);
        float inv = 1.f / (e0 + e1);
        wSm[2 * p * 64 + r] = e0 * inv;
        wSm[(2 * p + 1) * 64 + r] = e1 * inv;
    }
    __syncthreads();
    upack(R2[0], em, 0, 0);  // u_m
    upack(R2[1], em, 1, 1);
    __syncthreads();

    // ---------------- V_m (Wvm, phase 1) ----------------
    float mla0[4][4] = {}, mla1[4][4] = {};
    mbar_wait(mb, 1);
    mma_block(R2[0], WS, mla0, rb, c32, g, t);
    mma_block(R2[1], WS, mla1, rb, c32, g, t);
    __syncthreads();
    copy_w(4);  // Wvd -> phase 0
    upack(R3[0], ed, 0, 2);  // u_d (hides Wvd copy)
    upack(R3[1], ed, 1, 3);
    __syncthreads();

    // ---------------- V_d (Wvd, phase 0) + ne ----------------
    mbar_wait(mb, 0);
    {
        float dla[4][4] = {};
        mma_block(R3[0], WS, dla, rb, c32, g, t);
#pragma unroll
        for (int nt = 0; nt < 4; nt++) {
            int c = cb + nt * 8;
            *(uint2*)(R2[0] + r1 * LDW + c) =
                pack2(mla0[nt][0] * dla[nt][0], mla0[nt][1] * dla[nt][1]);
            *(uint2*)(R2[0] + r2 * LDW + c) =
                pack2(mla0[nt][2] * dla[nt][2], mla0[nt][3] * dla[nt][3]);
        }
    }
    {
        float dla[4][4] = {};
        mma_block(R3[1], WS, dla, rb, c32, g, t);
#pragma unroll
        for (int nt = 0; nt < 4; nt++) {
            int c = cb + nt * 8;
            *(uint2*)(R2[1] + r1 * LDW + c) =
                pack2(mla1[nt][0] * dla[nt][0], mla1[nt][1] * dla[nt][1]);
            *(uint2*)(R2[1] + r2 * LDW + c) =
                pack2(mla1[nt][2] * dla[nt][2], mla1[nt][3] * dla[nt][3]);
        }
    }
    __syncthreads();
    copy_w(5);  // W1 -> phase 1

    // ---------------- head (W1, phase 1) ----------------
    mbar_wait(mb, 1);
    {
        float ah0[4][4] = {}, ah1[4][4] = {};
        mma_block(R2[0], WS, ah0, rb, c32, g, t);
        mma_block(R2[1], WS, ah1, rb, c32, g, t);
#pragma unroll
        for (int tau = 0; tau < 2; tau++) {
            const float(*acc)[4] = tau ? ah1 : ah0;
            float pa = 0.f, pb = 0.f;
#pragma unroll
            for (int nt = 0; nt < 4; nt++) {
                int c = cb + nt * 8;
                float2 wv = *(const float2*)(sW2 + c);
                pa += fmaxf(acc[nt][0], 0.f) * wv.x + fmaxf(acc[nt][1], 0.f) * wv.y;
                pb += fmaxf(acc[nt][2], 0.f) * wv.x + fmaxf(acc[nt][3], 0.f) * wv.y;
            }
#pragma unroll
            for (int o = 1; o < 4; o <<= 1) {
                pa += __shfl_xor_sync(~0u, pa, o);
                pb += __shfl_xor_sync(~0u, pb, o);
            }
            if (t == 0) {
                red[tau * 256 + c32 * 64 + r1] = pa;
                red[tau * 256 + c32 * 64 + r2] = pb;
            }
        }
        __syncthreads();
        if (tid < 128) {
            int tau = tid >> 6, r = tid & 63;
            const float* p = red + tau * 256 + r;
            float P = p[0] + p[64] + p[128] + p[192];
            out[base + tau * 64 + r] = 1.f / (1.f + expf(-P));
        }
    }
}

// ---------------------------------------------------------------------------
extern "C" void kernel_launch(void* const* d_in, const int* in_sizes, int n_in,
                              void* d_out, int out_size) {
    const float* em    = (const float*)d_in[0];
    const float* ed    = (const float*)d_in[1];
    const float* W_gcn = (const float*)d_in[2];
    const float* Wq_m  = (const float*)d_in[3];
    const float* Wk_m  = (const float*)d_in[4];
    const float* Wv_m  = (const float*)d_in[5];
    const float* Wq_d  = (const float*)d_in[6];
    const float* Wk_d  = (const float*)d_in[7];
    const float* Wv_d  = (const float*)d_in[8];
    const float* W1    = (const float*)d_in[9];
    const float* W2    = (const float*)d_in[10];
    float* out = (float*)d_out;

    const int B = in_sizes[0] / C;
    const int smem_bytes = U_TOT * 4;  // 216,640

    precompute_M_kernel<<<dim3(C, 2), C>>>(Wq_m, Wk_m, Wq_d, Wk_d);
    bake_kernel<<<dim3(8192 / 256, 6), 256>>>(W_gcn, Wv_m, Wv_d, W1);

    cudaFuncSetAttribute(fused_kernel,
                         cudaFuncAttributeMaxDynamicSharedMemorySize, smem_bytes);
    fused_kernel<<<B / 128, THREADS, smem_bytes>>>(em, ed, W2, out);
}